// round 14
// baseline (speedup 1.0000x reference)
#include <cuda_runtime.h>
#include <math.h>

// ---------------------------------------------------------------------------
// FCOS3D target assignment — round 14: ILP-4.
// Each warp owns 128 consecutive points (thread: n, n+32, n+64, n+96).
// Shared per warp: one GT-table load, one point-bbox, one ballot/filter with
// full payload staging, one candidate smem load per scan step serving FOUR
// argmin updates. Epilogue = 4 independent chains. Coalesced bt3d writeback
// via per-warp smem tile (level-uniform warps), scalar fallback otherwise.
// 64-thread blocks keep the grid at 484 blocks (balanced 4-vs-3 per SM).
// ---------------------------------------------------------------------------

#define NLVL 5
#define NPTS 30929
#define INF_ 1.0e8f
#define NWARP 2
#define PPT  4               // points per thread
#define WSPAN (32 * PPT)     // 128 points per warp

__device__ __constant__ int   c_off[NLVL + 1] = {0, 23200, 29000, 30450, 30825, 30929};
__device__ __constant__ int   c_w[NLVL]       = {200, 100, 50, 25, 13};
__device__ __constant__ unsigned c_wmagic[NLVL] = {21474837u, 42949673u, 85899346u, 171798692u, 330382100u};
__device__ __constant__ float c_s[NLVL]       = {8.f, 16.f, 32.f, 64.f, 128.f};
__device__ __constant__ float c_xmax[NLVL]    = {1596.f, 1592.f, 1584.f, 1568.f, 1600.f};
__device__ __constant__ float c_inv_s[NLVL]   = {0.125f, 0.0625f, 0.03125f, 0.015625f, 0.0078125f};
__device__ __constant__ float c_cent_k[NLVL]  = {
    -2.5f / (1.414f * 8.f   * 1.5f),
    -2.5f / (1.414f * 16.f  * 1.5f),
    -2.5f / (1.414f * 32.f  * 1.5f),
    -2.5f / (1.414f * 64.f  * 1.5f),
    -2.5f / (1.414f * 128.f * 1.5f)};
__device__ __constant__ float c_r0[NLVL]      = {-1.f, 48.f, 96.f, 192.f, 384.f};
__device__ __constant__ float c_r1[NLVL]      = {48.f, 96.f, 192.f, 384.f, 1.0e8f};

// atan(a/b) for b > 0 (guaranteed: g3d[:,2] = |normal|+1 >= 1).
__device__ __forceinline__ float fast_atan2_pos(float a, float b) {
    const float t  = __fdividef(a, b);
    const float at = fabsf(t);
    const bool  inv = at > 1.0f;
    const float z  = inv ? __fdividef(1.0f, at) : at;
    const float z2 = z * z;
    float r = -0.0117212f;
    r = fmaf(r, z2,  0.05265332f);
    r = fmaf(r, z2, -0.11643287f);
    r = fmaf(r, z2,  0.19354346f);
    r = fmaf(r, z2, -0.33262347f);
    r = fmaf(r, z2,  0.99997726f);
    r = r * z;
    if (inv) r = 1.57079632679f - r;
    return copysignf(r, t);
}

struct Pt { int lvl, p; float x, y, r0, r1, rad; bool valid; };

__device__ __forceinline__ Pt make_pt(int n_raw) {
    Pt q;
    q.valid = (n_raw < NPTS);
    const int n = q.valid ? n_raw : (NPTS - 1);
    int lvl = 0;
#pragma unroll
    for (int i = 1; i < NLVL; i++)
        if (n >= c_off[i]) lvl = i;
    q.lvl = lvl;
    q.p   = n - c_off[lvl];
    const float s = c_s[lvl];
    const int row = (int)__umulhi((unsigned)q.p, c_wmagic[lvl]);
    const int col = q.p - row * c_w[lvl];
    q.x   = fmaf((float)col, s, 0.5f * s);
    q.y   = fmaf((float)row, s, 0.5f * s);
    q.r0  = c_r0[lvl];
    q.r1  = c_r1[lvl];
    q.rad = s * 1.5f;
    return q;
}

__global__ void __launch_bounds__(32 * NWARP)
fcos3d_target_kernel(
    const float* __restrict__ gt_bboxes,    // (B, M, 4)
    const float* __restrict__ g3d,          // (B, M, 9)
    const int*   __restrict__ gl3d,         // (B, M)
    const float* __restrict__ centers2d,    // (B, M, 2)
    const float* __restrict__ depths,       // (B, M)
    const int*   __restrict__ attrs,        // (B, M)
    float*       __restrict__ out,
    int M, int B)
{
    const int b    = blockIdx.y;
    const int tid  = threadIdx.x;
    const int lane = tid & 31;
    const int wid  = tid >> 5;

    __shared__ float4 s_cbb[NWARP][64];
    __shared__ float2 s_cc[NWARP][64];
    // payload: [g0,g2,g3,g4,g5,g6,g7,g8,depth,label,attr,pad]
    __shared__ float  s_pay[NWARP][64][12];
    // staged bt3d rows: WSPAN points x 9 floats per warp
    __shared__ float  s_bt[NWARP][WSPAN * 9];

    // ---- four points per thread: warp covers WSPAN consecutive n ----
    const int wbase = (blockIdx.x * NWARP + wid) * WSPAN;
    Pt P[PPT];
#pragma unroll
    for (int e = 0; e < PPT; e++)
        P[e] = make_pt(wbase + e * 32 + lane);

    // ---- issue independent global loads up front ----
    const float2* cptr = reinterpret_cast<const float2*>(centers2d) + (size_t)b * M;
    const float4* bptr = reinterpret_cast<const float4*>(gt_bboxes) + (size_t)b * M;

    float2 myc[2];
#pragma unroll
    for (int r = 0; r < 2; r++) {
        const int m = r * 32 + lane;
        myc[r] = (m < M) ? cptr[m] : make_float2(-2e30f, -2e30f);
    }

    // GT0 payload prefetch (broadcast; background majority; shared by all pts).
    const int gi0 = b * M;
    const float4* g0v = reinterpret_cast<const float4*>(g3d + (size_t)gi0 * 9);
    const float4 q0 = g0v[0];
    const float4 q1 = g0v[1];
    const float z_g0 = q0.x, z_g2 = q0.z, z_g3 = q0.w, z_g4 = q1.x;
    const float z_g5 = q1.y, z_g6 = q1.z, z_g7 = q1.w;
    const float z_g8 = g3d[(size_t)gi0 * 9 + 8];
    const float z_d  = depths[gi0];
    const float z_l  = (float)gl3d[gi0];
    const float z_a  = (float)attrs[gi0];
    const float2 c0  = cptr[0];

    // ---- warp point-bbox: first point of P[0], last point of P[PPT-1] ----
    const float xf = __shfl_sync(0xffffffffu, P[0].x, 0);
    const float yf = __shfl_sync(0xffffffffu, P[0].y, 0);
    const int   lf = __shfl_sync(0xffffffffu, P[0].lvl, 0);
    const float xl = __shfl_sync(0xffffffffu, P[PPT-1].x, 31);
    const float yl = __shfl_sync(0xffffffffu, P[PPT-1].y, 31);
    const int   ll = __shfl_sync(0xffffffffu, P[PPT-1].lvl, 31);

    const bool uniform = (lf == ll) && (wbase + WSPAN <= NPTS);

    float bxmin, bxmax, bymin, bymax;
    if (lf == ll) {
        const float rmx = c_s[lf] * 1.5f;
        const bool multirow = (yl != yf);
        bymin = yf - rmx;
        bymax = yl + rmx;
        bxmin = (multirow ? 0.5f * c_s[lf] : xf) - rmx;
        bxmax = (multirow ? c_xmax[lf] : xl) + rmx;
    } else {  // level boundary inside warp span (rare): all-pass
        bxmin = -3e38f; bxmax = 3e38f; bymin = -3e38f; bymax = 3e38f;
    }

    // ---- ballot filter; owners stage bbox + center + full payload ----
    int cnt = 0;
#pragma unroll
    for (int r = 0; r < 2; r++) {
        const int m = r * 32 + lane;
        const bool ok = (m < M) &
                        (myc[r].x >= bxmin) & (myc[r].x <= bxmax) &
                        (myc[r].y >= bymin) & (myc[r].y <= bymax);
        const unsigned mask = __ballot_sync(0xffffffffu, ok);
        if (ok) {
            const int pos = cnt + __popc(mask & ((1u << lane) - 1u));
            s_cbb[wid][pos] = bptr[m];
            s_cc[wid][pos]  = myc[r];
            const int gi = b * M + m;
            const float* g = g3d + (size_t)gi * 9;
            float* sp = s_pay[wid][pos];
            sp[0] = g[0]; sp[1] = g[2]; sp[2] = g[3]; sp[3] = g[4];
            sp[4] = g[5]; sp[5] = g[6]; sp[6] = g[7]; sp[7] = g[8];
            sp[8] = depths[gi];
            sp[9]  = (float)gl3d[gi];
            sp[10] = (float)attrs[gi];
        }
        cnt += __popc(mask);
    }
    __syncwarp();

    // ---- argmin for all PPT points per candidate load ----
    float best[PPT];
    int   bk[PPT];
#pragma unroll
    for (int e = 0; e < PPT; e++) { best[e] = INF_; bk[e] = -1; }

    for (int k = 0; k < cnt; k++) {
        const float4 bb = s_cbb[wid][k];
        const float2 c  = s_cc[wid][k];
#pragma unroll
        for (int e = 0; e < PPT; e++) {
            const float dx = P[e].x - c.x, dy = P[e].y - c.y;
            const float mrd = fmaxf(fmaxf(P[e].x - bb.x, P[e].y - bb.y),
                                    fmaxf(bb.z - P[e].x, bb.w - P[e].y));
            const bool ok = (mrd >= P[e].r0) & (mrd <= P[e].r1) &
                            (fmaxf(fabsf(dx), fabsf(dy)) < P[e].rad);
            const float d2 = ok ? fmaf(dx, dx, dy * dy) : INF_;
            if (d2 < best[e]) { best[e] = d2; bk[e] = k; }
        }
    }

    const int BN = B * NPTS;
    int baseP[PPT];

    // ---- epilogue: values + bt3d rows to smem (PPT independent chains) ----
#pragma unroll
    for (int e = 0; e < PPT; e++) {
        baseP[e] = -1;
        if (!P[e].valid) continue;

        const bool bg = (bk[e] < 0);
        float2 c = c0;
        float g0_ = z_g0, g2_ = z_g2, g3_ = z_g3, g4_ = z_g4;
        float g5_ = z_g5, g6_ = z_g6, g7_ = z_g7, g8_ = z_g8;
        float d_ = z_d, l_ = z_l, a_ = z_a;
        if (!bg) {
            c = s_cc[wid][bk[e]];
            const float* sp = s_pay[wid][bk[e]];
            g0_ = sp[0]; g2_ = sp[1]; g3_ = sp[2]; g4_ = sp[3];
            g5_ = sp[4]; g6_ = sp[5]; g7_ = sp[6]; g8_ = sp[7];
            d_  = sp[8]; l_ = sp[9];  a_ = sp[10];
        }

        const float dx = P[e].x - c.x;
        const float dy = P[e].y - c.y;
        const float yaw  = -fast_atan2_pos(g0_, g2_) + g6_;
        const float cent = __expf(c_cent_k[P[e].lvl] * sqrtf(fmaf(dx, dx, dy * dy)));

        const int npl  = c_off[P[e].lvl + 1] - c_off[P[e].lvl];
        const int base = c_off[P[e].lvl] * B + b * npl + P[e].p;
        baseP[e] = base;
        const float inv_s = c_inv_s[P[e].lvl];

        out[base]           = bg ? 10.f : l_;    // coalesced
        out[10 * BN + base] = cent;
        out[11 * BN + base] = bg ? 9.f : a_;

        float* sb = &s_bt[wid][(e * 32 + lane) * 9];
        sb[0] = dx * inv_s;
        sb[1] = dy * inv_s;
        sb[2] = d_;
        sb[3] = g3_;
        sb[4] = g4_;
        sb[5] = g5_;
        sb[6] = yaw;
        sb[7] = g7_;
        sb[8] = g8_;
    }
    __syncwarp();

    // ---- bt3d writeback ----
    if (uniform) {
        const int npl_f = c_off[lf + 1] - c_off[lf];
        const int base0 = c_off[lf] * B + b * npl_f + (wbase - c_off[lf]);
        float* dst = out + BN + (size_t)base0 * 9;
        const float* src = &s_bt[wid][0];
#pragma unroll
        for (int k = 0; k < 9 * PPT; k++)        // 36*32 = 1152 floats, coalesced
            dst[k * 32 + lane] = src[k * 32 + lane];
    } else {
#pragma unroll
        for (int e = 0; e < PPT; e++) {
            if (baseP[e] < 0) continue;
            float* bo = out + BN + (size_t)baseP[e] * 9;
            const float* sb = &s_bt[wid][(e * 32 + lane) * 9];
#pragma unroll
            for (int i = 0; i < 9; i++) bo[i] = sb[i];
        }
    }
}

extern "C" void kernel_launch(void* const* d_in, const int* in_sizes, int n_in,
                              void* d_out, int out_size)
{
    const float* gt_bboxes = (const float*)d_in[0];
    const float* g3d       = (const float*)d_in[2];
    const int*   gl3d      = (const int*)  d_in[3];
    const float* centers2d = (const float*)d_in[4];
    const float* depths    = (const float*)d_in[5];
    const int*   attrs     = (const int*)  d_in[6];
    float* out = (float*)d_out;

    const int B = out_size / (12 * NPTS);
    const int M = in_sizes[1] / B;

    const int threads = 32 * NWARP;               // 64 threads, 2 warps x 128 pts
    const int pts_per_block = NWARP * WSPAN;      // 256
    dim3 grid((NPTS + pts_per_block - 1) / pts_per_block, B);   // 121 x 4 = 484
    fcos3d_target_kernel<<<grid, threads>>>(
        gt_bboxes, g3d, gl3d, centers2d, depths, attrs, out, M, B);
}

// round 15
// speedup vs baseline: 1.5000x; 1.5000x over previous
#include <cuda_runtime.h>
#include <math.h>

// ---------------------------------------------------------------------------
// FCOS3D target assignment — round 15: R13 ILP-2 data path, 2-warp blocks.
// Grid 968 (6.54 blocks/SM): single-wave imbalance drops from 4-vs-3 (1.33x,
// R13's 484x128thr) to 7-vs-6 (1.17x) without R12's warp-per-block overhead.
// Each warp owns 64 consecutive points (thread: n and n+32). Shared per warp:
// one GT-table load, one point-bbox (2 shuffled endpoints), one ballot filter
// with full payload staging, one candidate smem load per scan step serving
// both points. bt3d staged in smem, written back fully coalesced for
// level-uniform warps.
// ---------------------------------------------------------------------------

#define NLVL 5
#define NPTS 30929
#define INF_ 1.0e8f
#define NWARP 2

__device__ __constant__ int   c_off[NLVL + 1] = {0, 23200, 29000, 30450, 30825, 30929};
__device__ __constant__ int   c_w[NLVL]       = {200, 100, 50, 25, 13};
__device__ __constant__ unsigned c_wmagic[NLVL] = {21474837u, 42949673u, 85899346u, 171798692u, 330382100u};
__device__ __constant__ float c_s[NLVL]       = {8.f, 16.f, 32.f, 64.f, 128.f};
__device__ __constant__ float c_xmax[NLVL]    = {1596.f, 1592.f, 1584.f, 1568.f, 1600.f};
__device__ __constant__ float c_inv_s[NLVL]   = {0.125f, 0.0625f, 0.03125f, 0.015625f, 0.0078125f};
__device__ __constant__ float c_cent_k[NLVL]  = {
    -2.5f / (1.414f * 8.f   * 1.5f),
    -2.5f / (1.414f * 16.f  * 1.5f),
    -2.5f / (1.414f * 32.f  * 1.5f),
    -2.5f / (1.414f * 64.f  * 1.5f),
    -2.5f / (1.414f * 128.f * 1.5f)};
__device__ __constant__ float c_r0[NLVL]      = {-1.f, 48.f, 96.f, 192.f, 384.f};
__device__ __constant__ float c_r1[NLVL]      = {48.f, 96.f, 192.f, 384.f, 1.0e8f};

// atan(a/b) for b > 0 (guaranteed: g3d[:,2] = |normal|+1 >= 1).
__device__ __forceinline__ float fast_atan2_pos(float a, float b) {
    const float t  = __fdividef(a, b);
    const float at = fabsf(t);
    const bool  inv = at > 1.0f;
    const float z  = inv ? __fdividef(1.0f, at) : at;
    const float z2 = z * z;
    float r = -0.0117212f;
    r = fmaf(r, z2,  0.05265332f);
    r = fmaf(r, z2, -0.11643287f);
    r = fmaf(r, z2,  0.19354346f);
    r = fmaf(r, z2, -0.33262347f);
    r = fmaf(r, z2,  0.99997726f);
    r = r * z;
    if (inv) r = 1.57079632679f - r;
    return copysignf(r, t);
}

struct Pt { int lvl, p; float x, y, r0, r1, rad; bool valid; };

__device__ __forceinline__ Pt make_pt(int n_raw) {
    Pt q;
    q.valid = (n_raw < NPTS);
    const int n = q.valid ? n_raw : (NPTS - 1);
    int lvl = 0;
#pragma unroll
    for (int i = 1; i < NLVL; i++)
        if (n >= c_off[i]) lvl = i;
    q.lvl = lvl;
    q.p   = n - c_off[lvl];
    const float s = c_s[lvl];
    const int row = (int)__umulhi((unsigned)q.p, c_wmagic[lvl]);
    const int col = q.p - row * c_w[lvl];
    q.x   = fmaf((float)col, s, 0.5f * s);
    q.y   = fmaf((float)row, s, 0.5f * s);
    q.r0  = c_r0[lvl];
    q.r1  = c_r1[lvl];
    q.rad = s * 1.5f;
    return q;
}

__global__ void __launch_bounds__(32 * NWARP)
fcos3d_target_kernel(
    const float* __restrict__ gt_bboxes,    // (B, M, 4)
    const float* __restrict__ g3d,          // (B, M, 9)
    const int*   __restrict__ gl3d,         // (B, M)
    const float* __restrict__ centers2d,    // (B, M, 2)
    const float* __restrict__ depths,       // (B, M)
    const int*   __restrict__ attrs,        // (B, M)
    float*       __restrict__ out,
    int M, int B)
{
    const int b    = blockIdx.y;
    const int tid  = threadIdx.x;
    const int lane = tid & 31;
    const int wid  = tid >> 5;

    __shared__ float4 s_cbb[NWARP][64];
    __shared__ float2 s_cc[NWARP][64];
    // payload: [g0,g2,g3,g4,g5,g6,g7,g8,depth,label,attr,pad]
    __shared__ float  s_pay[NWARP][64][12];
    // staged bt3d rows: 64 points x 9 floats per warp (stride-9, conflict-free)
    __shared__ float  s_bt[NWARP][64 * 9];

    // ---- two points per thread: warp covers 64 consecutive n ----
    const int wbase = (blockIdx.x * NWARP + wid) * 64;
    const Pt A  = make_pt(wbase + lane);
    const Pt Bp = make_pt(wbase + 32 + lane);

    // ---- issue independent global loads up front ----
    const float2* cptr = reinterpret_cast<const float2*>(centers2d) + (size_t)b * M;
    const float4* bptr = reinterpret_cast<const float4*>(gt_bboxes) + (size_t)b * M;

    float2 myc[2];
#pragma unroll
    for (int r = 0; r < 2; r++) {
        const int m = r * 32 + lane;
        myc[r] = (m < M) ? cptr[m] : make_float2(-2e30f, -2e30f);
    }

    // GT0 payload prefetch (broadcast; background majority; shared by A & B).
    const int gi0 = b * M;
    const float4* g0v = reinterpret_cast<const float4*>(g3d + (size_t)gi0 * 9);
    const float4 q0 = g0v[0];
    const float4 q1 = g0v[1];
    const float z_g0 = q0.x, z_g2 = q0.z, z_g3 = q0.w, z_g4 = q1.x;
    const float z_g5 = q1.y, z_g6 = q1.z, z_g7 = q1.w;
    const float z_g8 = g3d[(size_t)gi0 * 9 + 8];
    const float z_d  = depths[gi0];
    const float z_l  = (float)gl3d[gi0];
    const float z_a  = (float)attrs[gi0];
    const float2 c0  = cptr[0];

    // ---- warp point-bbox over the 64 points: first of A, last of B ----
    const float xf = __shfl_sync(0xffffffffu, A.x, 0);
    const float yf = __shfl_sync(0xffffffffu, A.y, 0);
    const int   lf = __shfl_sync(0xffffffffu, A.lvl, 0);
    const float xl = __shfl_sync(0xffffffffu, Bp.x, 31);
    const float yl = __shfl_sync(0xffffffffu, Bp.y, 31);
    const int   ll = __shfl_sync(0xffffffffu, Bp.lvl, 31);

    const bool uniform = (lf == ll) && (wbase + 64 <= NPTS);

    float bxmin, bxmax, bymin, bymax;
    if (lf == ll) {
        const float rmx = c_s[lf] * 1.5f;
        const bool multirow = (yl != yf);
        bymin = yf - rmx;
        bymax = yl + rmx;
        bxmin = (multirow ? 0.5f * c_s[lf] : xf) - rmx;
        bxmax = (multirow ? c_xmax[lf] : xl) + rmx;
    } else {  // level boundary inside warp span (rare): all-pass
        bxmin = -3e38f; bxmax = 3e38f; bymin = -3e38f; bymax = 3e38f;
    }

    // ---- ballot filter; owners stage bbox + center + full payload ----
    int cnt = 0;
#pragma unroll
    for (int r = 0; r < 2; r++) {
        const int m = r * 32 + lane;
        const bool ok = (m < M) &
                        (myc[r].x >= bxmin) & (myc[r].x <= bxmax) &
                        (myc[r].y >= bymin) & (myc[r].y <= bymax);
        const unsigned mask = __ballot_sync(0xffffffffu, ok);
        if (ok) {
            const int pos = cnt + __popc(mask & ((1u << lane) - 1u));
            s_cbb[wid][pos] = bptr[m];
            s_cc[wid][pos]  = myc[r];
            const int gi = b * M + m;
            const float* g = g3d + (size_t)gi * 9;
            float* sp = s_pay[wid][pos];
            sp[0] = g[0]; sp[1] = g[2]; sp[2] = g[3]; sp[3] = g[4];
            sp[4] = g[5]; sp[5] = g[6]; sp[6] = g[7]; sp[7] = g[8];
            sp[8] = depths[gi];
            sp[9]  = (float)gl3d[gi];
            sp[10] = (float)attrs[gi];
        }
        cnt += __popc(mask);
    }
    __syncwarp();

    // ---- argmin for BOTH points per candidate load ----
    float bestA = INF_, bestB = INF_;
    int   bkA = -1, bkB = -1;
    for (int k = 0; k < cnt; k++) {
        const float4 bb = s_cbb[wid][k];
        const float2 c  = s_cc[wid][k];
        {
            const float dx = A.x - c.x, dy = A.y - c.y;
            const float mrd = fmaxf(fmaxf(A.x - bb.x, A.y - bb.y),
                                    fmaxf(bb.z - A.x, bb.w - A.y));
            const bool ok = (mrd >= A.r0) & (mrd <= A.r1) &
                            (fmaxf(fabsf(dx), fabsf(dy)) < A.rad);
            const float d2 = ok ? fmaf(dx, dx, dy * dy) : INF_;
            if (d2 < bestA) { bestA = d2; bkA = k; }
        }
        {
            const float dx = Bp.x - c.x, dy = Bp.y - c.y;
            const float mrd = fmaxf(fmaxf(Bp.x - bb.x, Bp.y - bb.y),
                                    fmaxf(bb.z - Bp.x, bb.w - Bp.y));
            const bool ok = (mrd >= Bp.r0) & (mrd <= Bp.r1) &
                            (fmaxf(fabsf(dx), fabsf(dy)) < Bp.rad);
            const float d2 = ok ? fmaf(dx, dx, dy * dy) : INF_;
            if (d2 < bestB) { bestB = d2; bkB = k; }
        }
    }

    const int BN = B * NPTS;
    int baseP[2];

    // ---- epilogue: compute values; bt3d rows go to smem ----
#pragma unroll
    for (int e = 0; e < 2; e++) {
        const Pt&  P  = e ? Bp : A;
        const int  bk = e ? bkB : bkA;
        baseP[e] = -1;
        if (!P.valid) continue;

        const bool bg = (bk < 0);
        float2 c = c0;
        float g0_ = z_g0, g2_ = z_g2, g3_ = z_g3, g4_ = z_g4;
        float g5_ = z_g5, g6_ = z_g6, g7_ = z_g7, g8_ = z_g8;
        float d_ = z_d, l_ = z_l, a_ = z_a;
        if (!bg) {
            c = s_cc[wid][bk];
            const float* sp = s_pay[wid][bk];
            g0_ = sp[0]; g2_ = sp[1]; g3_ = sp[2]; g4_ = sp[3];
            g5_ = sp[4]; g6_ = sp[5]; g7_ = sp[6]; g8_ = sp[7];
            d_  = sp[8]; l_ = sp[9];  a_ = sp[10];
        }

        const float dx = P.x - c.x;
        const float dy = P.y - c.y;
        const float yaw  = -fast_atan2_pos(g0_, g2_) + g6_;
        const float cent = __expf(c_cent_k[P.lvl] * sqrtf(fmaf(dx, dx, dy * dy)));

        const int npl  = c_off[P.lvl + 1] - c_off[P.lvl];
        const int base = c_off[P.lvl] * B + b * npl + P.p;
        baseP[e] = base;
        const float inv_s = c_inv_s[P.lvl];

        out[base]           = bg ? 10.f : l_;   // coalesced (base consecutive)
        out[10 * BN + base] = cent;
        out[11 * BN + base] = bg ? 9.f : a_;

        float* sb = &s_bt[wid][(e * 32 + lane) * 9];  // stride-9: conflict-free
        sb[0] = dx * inv_s;
        sb[1] = dy * inv_s;
        sb[2] = d_;
        sb[3] = g3_;
        sb[4] = g4_;
        sb[5] = g5_;
        sb[6] = yaw;
        sb[7] = g7_;
        sb[8] = g8_;
    }
    __syncwarp();

    // ---- bt3d writeback ----
    if (uniform) {
        // 64 consecutive bases -> one contiguous 576-float run.
        const int npl_f = c_off[lf + 1] - c_off[lf];
        const int base0 = c_off[lf] * B + b * npl_f + (wbase - c_off[lf]);
        float* dst = out + BN + (size_t)base0 * 9;
        const float* src = &s_bt[wid][0];
#pragma unroll
        for (int k = 0; k < 18; k++)            // 18*32 = 576 floats, coalesced
            dst[k * 32 + lane] = src[k * 32 + lane];
    } else {
#pragma unroll
        for (int e = 0; e < 2; e++) {
            if (baseP[e] < 0) continue;
            float* bo = out + BN + (size_t)baseP[e] * 9;
            const float* sb = &s_bt[wid][(e * 32 + lane) * 9];
#pragma unroll
            for (int i = 0; i < 9; i++) bo[i] = sb[i];
        }
    }
}

extern "C" void kernel_launch(void* const* d_in, const int* in_sizes, int n_in,
                              void* d_out, int out_size)
{
    const float* gt_bboxes = (const float*)d_in[0];
    const float* g3d       = (const float*)d_in[2];
    const int*   gl3d      = (const int*)  d_in[3];
    const float* centers2d = (const float*)d_in[4];
    const float* depths    = (const float*)d_in[5];
    const int*   attrs     = (const int*)  d_in[6];
    float* out = (float*)d_out;

    const int B = out_size / (12 * NPTS);
    const int M = in_sizes[1] / B;

    const int threads = 32 * NWARP;               // 64 threads, 2 warps x 64 pts
    const int pts_per_block = NWARP * 64;         // 128
    dim3 grid((NPTS + pts_per_block - 1) / pts_per_block, B);   // 242 x 4 = 968
    fcos3d_target_kernel<<<grid, threads>>>(
        gt_bboxes, g3d, gl3d, centers2d, depths, attrs, out, M, B);
}

// round 16
// speedup vs baseline: 1.5055x; 1.0037x over previous
#include <cuda_runtime.h>
#include <math.h>

// ---------------------------------------------------------------------------
// FCOS3D target assignment — round 16: R15 (ILP-2, 2-warp/64-thread blocks,
// grid 968) + streaming stores (st.global.cs; output is write-once) and
// __ldg on the GT0 broadcast prefetch. Data path otherwise identical to R15.
// ---------------------------------------------------------------------------

#define NLVL 5
#define NPTS 30929
#define INF_ 1.0e8f
#define NWARP 2

__device__ __constant__ int   c_off[NLVL + 1] = {0, 23200, 29000, 30450, 30825, 30929};
__device__ __constant__ int   c_w[NLVL]       = {200, 100, 50, 25, 13};
__device__ __constant__ unsigned c_wmagic[NLVL] = {21474837u, 42949673u, 85899346u, 171798692u, 330382100u};
__device__ __constant__ float c_s[NLVL]       = {8.f, 16.f, 32.f, 64.f, 128.f};
__device__ __constant__ float c_xmax[NLVL]    = {1596.f, 1592.f, 1584.f, 1568.f, 1600.f};
__device__ __constant__ float c_inv_s[NLVL]   = {0.125f, 0.0625f, 0.03125f, 0.015625f, 0.0078125f};
__device__ __constant__ float c_cent_k[NLVL]  = {
    -2.5f / (1.414f * 8.f   * 1.5f),
    -2.5f / (1.414f * 16.f  * 1.5f),
    -2.5f / (1.414f * 32.f  * 1.5f),
    -2.5f / (1.414f * 64.f  * 1.5f),
    -2.5f / (1.414f * 128.f * 1.5f)};
__device__ __constant__ float c_r0[NLVL]      = {-1.f, 48.f, 96.f, 192.f, 384.f};
__device__ __constant__ float c_r1[NLVL]      = {48.f, 96.f, 192.f, 384.f, 1.0e8f};

// Streaming (evict-first) scalar store.
__device__ __forceinline__ void stcs(float* p, float v) {
    asm volatile("st.global.cs.f32 [%0], %1;" :: "l"(p), "f"(v) : "memory");
}

// atan(a/b) for b > 0 (guaranteed: g3d[:,2] = |normal|+1 >= 1).
__device__ __forceinline__ float fast_atan2_pos(float a, float b) {
    const float t  = __fdividef(a, b);
    const float at = fabsf(t);
    const bool  inv = at > 1.0f;
    const float z  = inv ? __fdividef(1.0f, at) : at;
    const float z2 = z * z;
    float r = -0.0117212f;
    r = fmaf(r, z2,  0.05265332f);
    r = fmaf(r, z2, -0.11643287f);
    r = fmaf(r, z2,  0.19354346f);
    r = fmaf(r, z2, -0.33262347f);
    r = fmaf(r, z2,  0.99997726f);
    r = r * z;
    if (inv) r = 1.57079632679f - r;
    return copysignf(r, t);
}

struct Pt { int lvl, p; float x, y, r0, r1, rad; bool valid; };

__device__ __forceinline__ Pt make_pt(int n_raw) {
    Pt q;
    q.valid = (n_raw < NPTS);
    const int n = q.valid ? n_raw : (NPTS - 1);
    int lvl = 0;
#pragma unroll
    for (int i = 1; i < NLVL; i++)
        if (n >= c_off[i]) lvl = i;
    q.lvl = lvl;
    q.p   = n - c_off[lvl];
    const float s = c_s[lvl];
    const int row = (int)__umulhi((unsigned)q.p, c_wmagic[lvl]);
    const int col = q.p - row * c_w[lvl];
    q.x   = fmaf((float)col, s, 0.5f * s);
    q.y   = fmaf((float)row, s, 0.5f * s);
    q.r0  = c_r0[lvl];
    q.r1  = c_r1[lvl];
    q.rad = s * 1.5f;
    return q;
}

__global__ void __launch_bounds__(32 * NWARP)
fcos3d_target_kernel(
    const float* __restrict__ gt_bboxes,    // (B, M, 4)
    const float* __restrict__ g3d,          // (B, M, 9)
    const int*   __restrict__ gl3d,         // (B, M)
    const float* __restrict__ centers2d,    // (B, M, 2)
    const float* __restrict__ depths,       // (B, M)
    const int*   __restrict__ attrs,        // (B, M)
    float*       __restrict__ out,
    int M, int B)
{
    const int b    = blockIdx.y;
    const int tid  = threadIdx.x;
    const int lane = tid & 31;
    const int wid  = tid >> 5;

    __shared__ float4 s_cbb[NWARP][64];
    __shared__ float2 s_cc[NWARP][64];
    // payload: [g0,g2,g3,g4,g5,g6,g7,g8,depth,label,attr,pad]
    __shared__ float  s_pay[NWARP][64][12];
    // staged bt3d rows: 64 points x 9 floats per warp (stride-9, conflict-free)
    __shared__ float  s_bt[NWARP][64 * 9];

    // ---- two points per thread: warp covers 64 consecutive n ----
    const int wbase = (blockIdx.x * NWARP + wid) * 64;
    const Pt A  = make_pt(wbase + lane);
    const Pt Bp = make_pt(wbase + 32 + lane);

    // ---- issue independent global loads up front ----
    const float2* cptr = reinterpret_cast<const float2*>(centers2d) + (size_t)b * M;
    const float4* bptr = reinterpret_cast<const float4*>(gt_bboxes) + (size_t)b * M;

    float2 myc[2];
#pragma unroll
    for (int r = 0; r < 2; r++) {
        const int m = r * 32 + lane;
        myc[r] = (m < M) ? cptr[m] : make_float2(-2e30f, -2e30f);
    }

    // GT0 payload prefetch (broadcast; background majority; shared by A & B).
    const int gi0 = b * M;
    const float4* g0v = reinterpret_cast<const float4*>(g3d + (size_t)gi0 * 9);
    const float4 q0 = __ldg(g0v);
    const float4 q1 = __ldg(g0v + 1);
    const float z_g0 = q0.x, z_g2 = q0.z, z_g3 = q0.w, z_g4 = q1.x;
    const float z_g5 = q1.y, z_g6 = q1.z, z_g7 = q1.w;
    const float z_g8 = __ldg(g3d + (size_t)gi0 * 9 + 8);
    const float z_d  = __ldg(depths + gi0);
    const float z_l  = (float)__ldg(gl3d + gi0);
    const float z_a  = (float)__ldg(attrs + gi0);
    const float2 c0  = __ldg(cptr);

    // ---- warp point-bbox over the 64 points: first of A, last of B ----
    const float xf = __shfl_sync(0xffffffffu, A.x, 0);
    const float yf = __shfl_sync(0xffffffffu, A.y, 0);
    const int   lf = __shfl_sync(0xffffffffu, A.lvl, 0);
    const float xl = __shfl_sync(0xffffffffu, Bp.x, 31);
    const float yl = __shfl_sync(0xffffffffu, Bp.y, 31);
    const int   ll = __shfl_sync(0xffffffffu, Bp.lvl, 31);

    const bool uniform = (lf == ll) && (wbase + 64 <= NPTS);

    float bxmin, bxmax, bymin, bymax;
    if (lf == ll) {
        const float rmx = c_s[lf] * 1.5f;
        const bool multirow = (yl != yf);
        bymin = yf - rmx;
        bymax = yl + rmx;
        bxmin = (multirow ? 0.5f * c_s[lf] : xf) - rmx;
        bxmax = (multirow ? c_xmax[lf] : xl) + rmx;
    } else {  // level boundary inside warp span (rare): all-pass
        bxmin = -3e38f; bxmax = 3e38f; bymin = -3e38f; bymax = 3e38f;
    }

    // ---- ballot filter; owners stage bbox + center + full payload ----
    int cnt = 0;
#pragma unroll
    for (int r = 0; r < 2; r++) {
        const int m = r * 32 + lane;
        const bool ok = (m < M) &
                        (myc[r].x >= bxmin) & (myc[r].x <= bxmax) &
                        (myc[r].y >= bymin) & (myc[r].y <= bymax);
        const unsigned mask = __ballot_sync(0xffffffffu, ok);
        if (ok) {
            const int pos = cnt + __popc(mask & ((1u << lane) - 1u));
            s_cbb[wid][pos] = bptr[m];
            s_cc[wid][pos]  = myc[r];
            const int gi = b * M + m;
            const float* g = g3d + (size_t)gi * 9;
            float* sp = s_pay[wid][pos];
            sp[0] = g[0]; sp[1] = g[2]; sp[2] = g[3]; sp[3] = g[4];
            sp[4] = g[5]; sp[5] = g[6]; sp[6] = g[7]; sp[7] = g[8];
            sp[8] = depths[gi];
            sp[9]  = (float)gl3d[gi];
            sp[10] = (float)attrs[gi];
        }
        cnt += __popc(mask);
    }
    __syncwarp();

    // ---- argmin for BOTH points per candidate load ----
    float bestA = INF_, bestB = INF_;
    int   bkA = -1, bkB = -1;
    for (int k = 0; k < cnt; k++) {
        const float4 bb = s_cbb[wid][k];
        const float2 c  = s_cc[wid][k];
        {
            const float dx = A.x - c.x, dy = A.y - c.y;
            const float mrd = fmaxf(fmaxf(A.x - bb.x, A.y - bb.y),
                                    fmaxf(bb.z - A.x, bb.w - A.y));
            const bool ok = (mrd >= A.r0) & (mrd <= A.r1) &
                            (fmaxf(fabsf(dx), fabsf(dy)) < A.rad);
            const float d2 = ok ? fmaf(dx, dx, dy * dy) : INF_;
            if (d2 < bestA) { bestA = d2; bkA = k; }
        }
        {
            const float dx = Bp.x - c.x, dy = Bp.y - c.y;
            const float mrd = fmaxf(fmaxf(Bp.x - bb.x, Bp.y - bb.y),
                                    fmaxf(bb.z - Bp.x, bb.w - Bp.y));
            const bool ok = (mrd >= Bp.r0) & (mrd <= Bp.r1) &
                            (fmaxf(fabsf(dx), fabsf(dy)) < Bp.rad);
            const float d2 = ok ? fmaf(dx, dx, dy * dy) : INF_;
            if (d2 < bestB) { bestB = d2; bkB = k; }
        }
    }

    const int BN = B * NPTS;
    int baseP[2];

    // ---- epilogue: compute values; bt3d rows go to smem ----
#pragma unroll
    for (int e = 0; e < 2; e++) {
        const Pt&  P  = e ? Bp : A;
        const int  bk = e ? bkB : bkA;
        baseP[e] = -1;
        if (!P.valid) continue;

        const bool bg = (bk < 0);
        float2 c = c0;
        float g0_ = z_g0, g2_ = z_g2, g3_ = z_g3, g4_ = z_g4;
        float g5_ = z_g5, g6_ = z_g6, g7_ = z_g7, g8_ = z_g8;
        float d_ = z_d, l_ = z_l, a_ = z_a;
        if (!bg) {
            c = s_cc[wid][bk];
            const float* sp = s_pay[wid][bk];
            g0_ = sp[0]; g2_ = sp[1]; g3_ = sp[2]; g4_ = sp[3];
            g5_ = sp[4]; g6_ = sp[5]; g7_ = sp[6]; g8_ = sp[7];
            d_  = sp[8]; l_ = sp[9];  a_ = sp[10];
        }

        const float dx = P.x - c.x;
        const float dy = P.y - c.y;
        const float yaw  = -fast_atan2_pos(g0_, g2_) + g6_;
        const float cent = __expf(c_cent_k[P.lvl] * sqrtf(fmaf(dx, dx, dy * dy)));

        const int npl  = c_off[P.lvl + 1] - c_off[P.lvl];
        const int base = c_off[P.lvl] * B + b * npl + P.p;
        baseP[e] = base;
        const float inv_s = c_inv_s[P.lvl];

        stcs(out + base,           bg ? 10.f : l_);   // labels_3d (coalesced)
        stcs(out + 10 * BN + base, cent);             // centerness
        stcs(out + 11 * BN + base, bg ? 9.f : a_);    // attr

        float* sb = &s_bt[wid][(e * 32 + lane) * 9];  // stride-9: conflict-free
        sb[0] = dx * inv_s;
        sb[1] = dy * inv_s;
        sb[2] = d_;
        sb[3] = g3_;
        sb[4] = g4_;
        sb[5] = g5_;
        sb[6] = yaw;
        sb[7] = g7_;
        sb[8] = g8_;
    }
    __syncwarp();

    // ---- bt3d writeback ----
    if (uniform) {
        // 64 consecutive bases -> one contiguous 576-float run.
        const int npl_f = c_off[lf + 1] - c_off[lf];
        const int base0 = c_off[lf] * B + b * npl_f + (wbase - c_off[lf]);
        float* dst = out + BN + (size_t)base0 * 9;
        const float* src = &s_bt[wid][0];
#pragma unroll
        for (int k = 0; k < 18; k++)            // 18*32 = 576 floats, coalesced
            stcs(dst + k * 32 + lane, src[k * 32 + lane]);
    } else {
#pragma unroll
        for (int e = 0; e < 2; e++) {
            if (baseP[e] < 0) continue;
            float* bo = out + BN + (size_t)baseP[e] * 9;
            const float* sb = &s_bt[wid][(e * 32 + lane) * 9];
#pragma unroll
            for (int i = 0; i < 9; i++) stcs(bo + i, sb[i]);
        }
    }
}

extern "C" void kernel_launch(void* const* d_in, const int* in_sizes, int n_in,
                              void* d_out, int out_size)
{
    const float* gt_bboxes = (const float*)d_in[0];
    const float* g3d       = (const float*)d_in[2];
    const int*   gl3d      = (const int*)  d_in[3];
    const float* centers2d = (const float*)d_in[4];
    const float* depths    = (const float*)d_in[5];
    const int*   attrs     = (const int*)  d_in[6];
    float* out = (float*)d_out;

    const int B = out_size / (12 * NPTS);
    const int M = in_sizes[1] / B;

    const int threads = 32 * NWARP;               // 64 threads, 2 warps x 64 pts
    const int pts_per_block = NWARP * 64;         // 128
    dim3 grid((NPTS + pts_per_block - 1) / pts_per_block, B);   // 242 x 4 = 968
    fcos3d_target_kernel<<<grid, threads>>>(
        gt_bboxes, g3d, gl3d, centers2d, depths, attrs, out, M, B);
}